// round 1
// baseline (speedup 1.0000x reference)
#include <cuda_runtime.h>
#include <cuda_bf16.h>

#define HD   128     // head dim
#define TOPK 64
#define SQL  1024
#define SKV  4096
#define NH   16

__global__ __launch_bounds__(128, 8)
void dsa_sparse_attn_kernel(const float* __restrict__ q,
                            const float* __restrict__ k,
                            const float* __restrict__ v,
                            const int*   __restrict__ topk_indices,
                            const float* __restrict__ topk_scores,
                            float* __restrict__ out) {
    const int sq   = blockIdx.x;
    const int h    = blockIdx.y;
    const int tid  = threadIdx.x;      // 0..127
    const int lane = tid & 31;
    const int warp = tid >> 5;

    __shared__ float q_s[HD];
    __shared__ int   idx_s[TOPK];
    __shared__ float sc_s[TOPK];
    __shared__ float w_s[TOPK];

    // Stage q row and indices
    q_s[tid] = q[((size_t)h * SQL + sq) * HD + tid];
    if (tid < TOPK) {
        idx_s[tid] = topk_indices[(size_t)sq * TOPK + tid];
    }
    __syncthreads();

    const float4* q4 = reinterpret_cast<const float4*>(q_s);
    const float4  qv = q4[lane];   // each warp's 32 lanes jointly hold full q

    const size_t kv_head_base = (size_t)h * SKV * HD;

    // ---- Score phase: warp w handles entries [w*16, w*16+16) ----
    #pragma unroll 4
    for (int i = 0; i < 16; i++) {
        const int t   = warp * 16 + i;
        const int row = idx_s[t];
        const float4* kr = reinterpret_cast<const float4*>(k + kv_head_base + (size_t)row * HD);
        const float4 kv4 = kr[lane];
        float p = qv.x * kv4.x + qv.y * kv4.y + qv.z * kv4.z + qv.w * kv4.w;
        #pragma unroll
        for (int o = 16; o > 0; o >>= 1)
            p += __shfl_xor_sync(0xffffffffu, p, o);
        if (lane == 0) sc_s[t] = p;
    }
    __syncthreads();

    // ---- Softmax + score-weight fusion (warp 0 only) ----
    // ref: w = softmax(s)*p; w /= (sum(w) + 1e-12)
    //   => w_t = e_t * p_t / (sum(e*p) + 1e-12 * sum(e))
    if (warp == 0) {
        const float scale = 0.088388347648318447f;  // 128^-0.5
        float s0 = sc_s[lane]      * scale;
        float s1 = sc_s[lane + 32] * scale;
        float m = fmaxf(s0, s1);
        #pragma unroll
        for (int o = 16; o > 0; o >>= 1)
            m = fmaxf(m, __shfl_xor_sync(0xffffffffu, m, o));
        const float p0 = topk_scores[(size_t)sq * TOPK + lane];
        const float p1 = topk_scores[(size_t)sq * TOPK + lane + 32];
        const float e0 = __expf(s0 - m);
        const float e1 = __expf(s1 - m);
        const float w0 = e0 * p0;
        const float w1 = e1 * p1;
        float se = e0 + e1;
        float sw = w0 + w1;
        #pragma unroll
        for (int o = 16; o > 0; o >>= 1) {
            se += __shfl_xor_sync(0xffffffffu, se, o);
            sw += __shfl_xor_sync(0xffffffffu, sw, o);
        }
        const float inv = 1.0f / (sw + 1e-12f * se);
        w_s[lane]      = w0 * inv;
        w_s[lane + 32] = w1 * inv;
    }
    __syncthreads();

    // ---- Output phase: thread tid owns out[.., tid]; 4 accumulators for MLP ----
    float acc0 = 0.f, acc1 = 0.f, acc2 = 0.f, acc3 = 0.f;
    #pragma unroll 4
    for (int t = 0; t < TOPK; t += 4) {
        const float* v0 = v + kv_head_base + (size_t)idx_s[t]     * HD;
        const float* v1 = v + kv_head_base + (size_t)idx_s[t + 1] * HD;
        const float* v2 = v + kv_head_base + (size_t)idx_s[t + 2] * HD;
        const float* v3 = v + kv_head_base + (size_t)idx_s[t + 3] * HD;
        acc0 += w_s[t]     * v0[tid];
        acc1 += w_s[t + 1] * v1[tid];
        acc2 += w_s[t + 2] * v2[tid];
        acc3 += w_s[t + 3] * v3[tid];
    }
    out[((size_t)h * SQL + sq) * HD + tid] = (acc0 + acc1) + (acc2 + acc3);
}

extern "C" void kernel_launch(void* const* d_in, const int* in_sizes, int n_in,
                              void* d_out, int out_size) {
    const float* q   = (const float*)d_in[0];
    const float* k   = (const float*)d_in[1];
    const float* v   = (const float*)d_in[2];
    const int*   ti  = (const int*)  d_in[3];
    const float* ts  = (const float*)d_in[4];
    float* out = (float*)d_out;

    dim3 grid(SQL, NH);
    dsa_sparse_attn_kernel<<<grid, 128>>>(q, k, v, ti, ts, out);
}

// round 2
// speedup vs baseline: 1.1266x; 1.1266x over previous
#include <cuda_runtime.h>
#include <cuda_fp16.h>

#define HD   128     // head dim
#define TOPK 64
#define SQL  1024
#define SKV  4096
#define NH   16
#define KV_ELEMS (NH * SKV * HD)   // 8,388,608 per tensor

// fp16 copies of K and V (16 MB each) — gathered at half the L1 wavefront cost.
__device__ __half2 g_k16[KV_ELEMS / 2];
__device__ __half2 g_v16[KV_ELEMS / 2];

// ---- Pre-pass: fp32 -> fp16 conversion of K and V ----
__global__ __launch_bounds__(256)
void convert_kv_kernel(const float4* __restrict__ k, const float4* __restrict__ v) {
    const int i = blockIdx.x * blockDim.x + threadIdx.x;  // over KV_ELEMS/4
    uint2* kd = reinterpret_cast<uint2*>(g_k16);
    uint2* vd = reinterpret_cast<uint2*>(g_v16);

    float4 a = k[i];
    __half2 k0 = __floats2half2_rn(a.x, a.y);
    __half2 k1 = __floats2half2_rn(a.z, a.w);
    uint2 kp;
    kp.x = *reinterpret_cast<unsigned*>(&k0);
    kp.y = *reinterpret_cast<unsigned*>(&k1);
    kd[i] = kp;

    float4 b = v[i];
    __half2 v0 = __floats2half2_rn(b.x, b.y);
    __half2 v1 = __floats2half2_rn(b.z, b.w);
    uint2 vp;
    vp.x = *reinterpret_cast<unsigned*>(&v0);
    vp.y = *reinterpret_cast<unsigned*>(&v1);
    vd[i] = vp;
}

// ---- Main sparse-attention kernel ----
__global__ __launch_bounds__(128)
void dsa_sparse_attn_kernel(const float* __restrict__ q,
                            const int*   __restrict__ topk_indices,
                            const float* __restrict__ topk_scores,
                            float* __restrict__ out) {
    const int sq   = blockIdx.x;
    const int h    = blockIdx.y;
    const int tid  = threadIdx.x;      // 0..127
    const int lane = tid & 31;
    const int warp = tid >> 5;

    __shared__ float  q_s[HD];
    __shared__ int    idx_s[TOPK];
    __shared__ float  sc_s[TOPK];
    __shared__ float  w_s[TOPK];
    __shared__ float2 red_s[HD / 2];   // cross-group reduction for V phase

    // Stage q row and indices
    q_s[tid] = q[((size_t)h * SQL + sq) * HD + tid];
    if (tid < TOPK) {
        idx_s[tid] = topk_indices[(size_t)sq * TOPK + tid];
    }
    __syncthreads();

    const float4* q4 = reinterpret_cast<const float4*>(q_s);
    const float4  qv = q4[lane];   // 32 lanes jointly hold full q (4 elems each)

    const size_t head_base2 = (size_t)h * SKV * (HD / 2);  // in half2 units

    // ---- Score phase: warp w handles entries [w*16, w*16+16) ----
    // Each lane loads 4 contiguous halves (8B) of the K row.
    #pragma unroll 4
    for (int i = 0; i < 16; i++) {
        const int t   = warp * 16 + i;
        const int row = idx_s[t];
        const uint2* kr = reinterpret_cast<const uint2*>(g_k16 + head_base2 + (size_t)row * (HD / 2));
        uint2 raw = kr[lane];
        __half2 h0 = *reinterpret_cast<__half2*>(&raw.x);
        __half2 h1 = *reinterpret_cast<__half2*>(&raw.y);
        float2 f0 = __half22float2(h0);
        float2 f1 = __half22float2(h1);
        float p = qv.x * f0.x + qv.y * f0.y + qv.z * f1.x + qv.w * f1.y;
        #pragma unroll
        for (int o = 16; o > 0; o >>= 1)
            p += __shfl_xor_sync(0xffffffffu, p, o);
        if (lane == 0) sc_s[t] = p;
    }
    __syncthreads();

    // ---- Softmax + score-weight fusion (warp 0) ----
    //   w_t = e_t * p_t / (sum(e*p) + 1e-12 * sum(e))
    if (warp == 0) {
        const float scale = 0.088388347648318447f;  // 128^-0.5
        float s0 = sc_s[lane]      * scale;
        float s1 = sc_s[lane + 32] * scale;
        float m = fmaxf(s0, s1);
        #pragma unroll
        for (int o = 16; o > 0; o >>= 1)
            m = fmaxf(m, __shfl_xor_sync(0xffffffffu, m, o));
        const float p0 = topk_scores[(size_t)sq * TOPK + lane];
        const float p1 = topk_scores[(size_t)sq * TOPK + lane + 32];
        const float e0 = __expf(s0 - m);
        const float e1 = __expf(s1 - m);
        const float w0 = e0 * p0;
        const float w1 = e1 * p1;
        float se = e0 + e1;
        float sw = w0 + w1;
        #pragma unroll
        for (int o = 16; o > 0; o >>= 1) {
            se += __shfl_xor_sync(0xffffffffu, se, o);
            sw += __shfl_xor_sync(0xffffffffu, sw, o);
        }
        const float inv = 1.0f / (sw + 1e-12f * se);
        w_s[lane]      = w0 * inv;
        w_s[lane + 32] = w1 * inv;
    }
    __syncthreads();

    // ---- Output phase ----
    // Two groups of 64 threads; group g handles rows t = g, g+2, ...
    // Thread (g, p) owns output dims [2p, 2p+1] via half2 loads.
    const int grp = tid >> 6;        // 0 or 1
    const int p   = tid & 63;        // half2 position in the row

    float2 accA = make_float2(0.f, 0.f);
    float2 accB = make_float2(0.f, 0.f);
    #pragma unroll 4
    for (int t = grp; t < TOPK; t += 4) {
        {
            const int row = idx_s[t];
            __half2 hv = g_v16[head_base2 + (size_t)row * (HD / 2) + p];
            float2 f = __half22float2(hv);
            const float w = w_s[t];
            accA.x += w * f.x;
            accA.y += w * f.y;
        }
        {
            const int row = idx_s[t + 2];
            __half2 hv = g_v16[head_base2 + (size_t)row * (HD / 2) + p];
            float2 f = __half22float2(hv);
            const float w = w_s[t + 2];
            accB.x += w * f.x;
            accB.y += w * f.y;
        }
    }
    accA.x += accB.x;
    accA.y += accB.y;

    if (grp == 1) {
        red_s[p] = accA;
    }
    __syncthreads();
    if (grp == 0) {
        float2 other = red_s[p];
        float2 r;
        r.x = accA.x + other.x;
        r.y = accA.y + other.y;
        float2* o2 = reinterpret_cast<float2*>(out + ((size_t)h * SQL + sq) * HD);
        o2[p] = r;
    }
}

extern "C" void kernel_launch(void* const* d_in, const int* in_sizes, int n_in,
                              void* d_out, int out_size) {
    const float* q   = (const float*)d_in[0];
    const float* k   = (const float*)d_in[1];
    const float* v   = (const float*)d_in[2];
    const int*   ti  = (const int*)  d_in[3];
    const float* ts  = (const float*)d_in[4];
    float* out = (float*)d_out;

    // Pre-pass: fp32 -> fp16 for K and V
    const int n4 = KV_ELEMS / 4;
    convert_kv_kernel<<<n4 / 256, 256>>>((const float4*)k, (const float4*)v);

    dim3 grid(SQL, NH);
    dsa_sparse_attn_kernel<<<grid, 128>>>(q, ti, ts, out);
}

// round 3
// speedup vs baseline: 1.5755x; 1.3985x over previous
#include <cuda_runtime.h>
#include <cuda_fp16.h>

#define HD   128     // head dim
#define TOPK 64
#define SQL  1024
#define SKV  4096
#define NH   16
#define KV_ELEMS (NH * SKV * HD)   // 8,388,608 per tensor

// fp16 copies of K and V (16 MB each)
__device__ __half2 g_k16[KV_ELEMS / 2];
__device__ __half2 g_v16[KV_ELEMS / 2];

// ---- Pre-pass: fp32 -> fp16 conversion of K and V ----
__global__ __launch_bounds__(256)
void convert_kv_kernel(const float4* __restrict__ k, const float4* __restrict__ v) {
    const int i = blockIdx.x * blockDim.x + threadIdx.x;  // over KV_ELEMS/4
    uint2* kd = reinterpret_cast<uint2*>(g_k16);
    uint2* vd = reinterpret_cast<uint2*>(g_v16);

    float4 a = k[i];
    __half2 k0 = __floats2half2_rn(a.x, a.y);
    __half2 k1 = __floats2half2_rn(a.z, a.w);
    uint2 kp;
    kp.x = *reinterpret_cast<unsigned*>(&k0);
    kp.y = *reinterpret_cast<unsigned*>(&k1);
    kd[i] = kp;

    float4 b = v[i];
    __half2 v0 = __floats2half2_rn(b.x, b.y);
    __half2 v1 = __floats2half2_rn(b.z, b.w);
    uint2 vp;
    vp.x = *reinterpret_cast<unsigned*>(&v0);
    vp.y = *reinterpret_cast<unsigned*>(&v1);
    vd[i] = vp;
}

// ---- Main sparse-attention kernel ----
// Block = (h, sq). 4 warps; warp w owns topk entries [w*16, w*16+16).
// Within each warp: lanes 0-15 process one row, lanes 16-31 a second row,
// each lane covering 8 head dims via one 16B load.
__global__ __launch_bounds__(128)
void dsa_sparse_attn_kernel(const float* __restrict__ q,
                            const int*   __restrict__ topk_indices,
                            const float* __restrict__ topk_scores,
                            float* __restrict__ out) {
    const int sq   = blockIdx.x;
    const int h    = blockIdx.y;
    const int tid  = threadIdx.x;      // 0..127
    const int lane = tid & 31;
    const int warp = tid >> 5;
    const int sub  = lane & 15;        // dim-group within the 16-lane half
    const int hlf  = lane >> 4;        // which row of the pair

    __shared__ float q_s[HD];
    __shared__ int   idx_s[TOPK];
    __shared__ float sc_s[TOPK];
    __shared__ float w_s[TOPK];
    __shared__ float red_s[4][HD];

    // Stage q row and indices
    q_s[tid] = q[((size_t)h * SQL + sq) * HD + tid];
    if (tid < TOPK) {
        idx_s[tid] = topk_indices[(size_t)sq * TOPK + tid];
    }
    __syncthreads();

    // q dims [sub*8, sub*8+8) in registers (same for both warp halves)
    const float4* q4 = reinterpret_cast<const float4*>(q_s);
    const float4 qa = q4[sub * 2];
    const float4 qb = q4[sub * 2 + 1];

    const size_t hb   = (size_t)h * SKV * (HD / 2);  // head base, half2 units
    const int    base = warp * 16;

    // ---- Score phase: 8 iterations, 2 rows per iteration ----
    #pragma unroll
    for (int i = 0; i < 8; i++) {
        const int t   = base + 2 * i + hlf;
        const int row = idx_s[t];
        const uint4* kr = reinterpret_cast<const uint4*>(g_k16 + hb + (size_t)row * (HD / 2));
        uint4 raw = kr[sub];
        float2 f0 = __half22float2(*reinterpret_cast<__half2*>(&raw.x));
        float2 f1 = __half22float2(*reinterpret_cast<__half2*>(&raw.y));
        float2 f2 = __half22float2(*reinterpret_cast<__half2*>(&raw.z));
        float2 f3 = __half22float2(*reinterpret_cast<__half2*>(&raw.w));
        float p = qa.x * f0.x + qa.y * f0.y + qa.z * f1.x + qa.w * f1.y
                + qb.x * f2.x + qb.y * f2.y + qb.z * f3.x + qb.w * f3.y;
        // reduce over the 16-lane half (both halves reduce in parallel)
        #pragma unroll
        for (int o = 8; o > 0; o >>= 1)
            p += __shfl_xor_sync(0xffffffffu, p, o);
        if (sub == 0) sc_s[t] = p;
    }
    __syncthreads();

    // ---- Softmax + score-weight fusion (warp 0) ----
    //   w_t = e_t * p_t / (sum(e*p) + 1e-12 * sum(e))
    if (warp == 0) {
        const float scale = 0.088388347648318447f;  // 128^-0.5
        float s0 = sc_s[lane]      * scale;
        float s1 = sc_s[lane + 32] * scale;
        float m = fmaxf(s0, s1);
        #pragma unroll
        for (int o = 16; o > 0; o >>= 1)
            m = fmaxf(m, __shfl_xor_sync(0xffffffffu, m, o));
        const float p0 = topk_scores[(size_t)sq * TOPK + lane];
        const float p1 = topk_scores[(size_t)sq * TOPK + lane + 32];
        const float e0 = __expf(s0 - m);
        const float e1 = __expf(s1 - m);
        const float w0 = e0 * p0;
        const float w1 = e1 * p1;
        float se = e0 + e1;
        float sw = w0 + w1;
        #pragma unroll
        for (int o = 16; o > 0; o >>= 1) {
            se += __shfl_xor_sync(0xffffffffu, se, o);
            sw += __shfl_xor_sync(0xffffffffu, sw, o);
        }
        const float inv = 1.0f / (sw + 1e-12f * se);
        w_s[lane]      = w0 * inv;
        w_s[lane + 32] = w1 * inv;
    }
    __syncthreads();

    // ---- V phase: same 2-rows-per-LDG layout; 8 dims per lane ----
    float a0 = 0.f, a1 = 0.f, a2 = 0.f, a3 = 0.f;
    float a4 = 0.f, a5 = 0.f, a6 = 0.f, a7 = 0.f;
    #pragma unroll
    for (int i = 0; i < 8; i++) {
        const int   t   = base + 2 * i + hlf;
        const int   row = idx_s[t];
        const float wgt = w_s[t];
        const uint4* vr = reinterpret_cast<const uint4*>(g_v16 + hb + (size_t)row * (HD / 2));
        uint4 raw = vr[sub];
        float2 f0 = __half22float2(*reinterpret_cast<__half2*>(&raw.x));
        float2 f1 = __half22float2(*reinterpret_cast<__half2*>(&raw.y));
        float2 f2 = __half22float2(*reinterpret_cast<__half2*>(&raw.z));
        float2 f3 = __half22float2(*reinterpret_cast<__half2*>(&raw.w));
        a0 += wgt * f0.x; a1 += wgt * f0.y;
        a2 += wgt * f1.x; a3 += wgt * f1.y;
        a4 += wgt * f2.x; a5 += wgt * f2.y;
        a6 += wgt * f3.x; a7 += wgt * f3.y;
    }
    // combine the two 16-lane halves (different rows, same dims)
    a0 += __shfl_xor_sync(0xffffffffu, a0, 16);
    a1 += __shfl_xor_sync(0xffffffffu, a1, 16);
    a2 += __shfl_xor_sync(0xffffffffu, a2, 16);
    a3 += __shfl_xor_sync(0xffffffffu, a3, 16);
    a4 += __shfl_xor_sync(0xffffffffu, a4, 16);
    a5 += __shfl_xor_sync(0xffffffffu, a5, 16);
    a6 += __shfl_xor_sync(0xffffffffu, a6, 16);
    a7 += __shfl_xor_sync(0xffffffffu, a7, 16);

    if (hlf == 0) {
        float4* r4 = reinterpret_cast<float4*>(&red_s[warp][sub * 8]);
        r4[0] = make_float4(a0, a1, a2, a3);
        r4[1] = make_float4(a4, a5, a6, a7);
    }
    __syncthreads();

    // cross-warp reduce + store (thread tid owns output dim tid)
    float r = red_s[0][tid] + red_s[1][tid] + red_s[2][tid] + red_s[3][tid];
    out[((size_t)h * SQL + sq) * HD + tid] = r;
}

extern "C" void kernel_launch(void* const* d_in, const int* in_sizes, int n_in,
                              void* d_out, int out_size) {
    const float* q   = (const float*)d_in[0];
    const float* k   = (const float*)d_in[1];
    const float* v   = (const float*)d_in[2];
    const int*   ti  = (const int*)  d_in[3];
    const float* ts  = (const float*)d_in[4];
    float* out = (float*)d_out;

    const int n4 = KV_ELEMS / 4;
    convert_kv_kernel<<<n4 / 256, 256>>>((const float4*)k, (const float4*)v);

    dim3 grid(SQL, NH);
    dsa_sparse_attn_kernel<<<grid, 128>>>(q, ti, ts, out);
}